// round 6
// baseline (speedup 1.0000x reference)
#include <cuda_runtime.h>
#include <cstdint>

// ---------------- problem dims ----------------
#define BDIM 32
#define TDIM 4096
#define DDIM 512
#define MDIM (BDIM * TDIM)          // 131072

// ---------------- GEMM tiling ----------------
#define TILE_M 128
#define TILE_N 128
#define BK 32                        // k floats per chunk
#define NCHUNK (DDIM / BK)           // 16
#define STAGES 3
#define ROWF 36                      // padded row stride (144B = 9*16B -> conflict-free ldmatrix)
#define A_FLOATS (TILE_M * ROWF)     // 4608
#define B_FLOATS (TILE_N * ROWF)     // 4608
#define STAGE_FLOATS (A_FLOATS + B_FLOATS)       // 9216
#define SMEM_BYTES (STAGES * STAGE_FLOATS * 4)   // 110592

#define NTHREADS 128                 // 4 warps, 64x64 warp tile

#define CHUNKS 32                    // softmax chunks = M-tiles per batch (4096/128)

// ---------------- scratch ----------------
__device__ float g_hr[(size_t)MDIM * DDIM];   // tf32-rounded h
__device__ float g_w1[DDIM * DDIM];
__device__ float g_w2[DDIM * DDIM];
__device__ float g_u[(size_t)MDIM * DDIM];    // tanh(...), tf32-rounded
__device__ float g_m[BDIM * CHUNKS * DDIM];
__device__ float g_z[BDIM * CHUNKS * DDIM];
__device__ float g_a[BDIM * CHUNKS * DDIM];
__device__ float g_r[BDIM * DDIM];

// ---------------- helpers ----------------
__device__ __forceinline__ uint32_t smem_u32(const void* p) {
    uint32_t a;
    asm("{ .reg .u64 t; cvta.to.shared.u64 t, %1; cvt.u32.u64 %0, t; }" : "=r"(a) : "l"(p));
    return a;
}
__device__ __forceinline__ void cp16(uint32_t dst, const void* src) {
    asm volatile("cp.async.cg.shared.global [%0], [%1], 16;" :: "r"(dst), "l"(src));
}
__device__ __forceinline__ void ldsm4(uint32_t* r, uint32_t addr) {
    asm volatile("ldmatrix.sync.aligned.m8n8.x4.shared.b16 {%0,%1,%2,%3}, [%4];"
                 : "=r"(r[0]), "=r"(r[1]), "=r"(r[2]), "=r"(r[3]) : "r"(addr));
}
__device__ __forceinline__ float rna_tf32(float x) {
    float y;
    asm("cvt.rna.tf32.f32 %0, %1;" : "=f"(y) : "f"(x));
    return y;
}
__device__ __forceinline__ void mma8(float* c, const uint32_t* a, const uint32_t* b) {
    asm volatile(
        "mma.sync.aligned.m16n8k8.row.col.f32.tf32.tf32.f32 "
        "{%0,%1,%2,%3}, {%4,%5,%6,%7}, {%8,%9}, {%0,%1,%2,%3};"
        : "+f"(c[0]), "+f"(c[1]), "+f"(c[2]), "+f"(c[3])
        : "r"(a[0]), "r"(a[1]), "r"(a[2]), "r"(a[3]), "r"(b[0]), "r"(b[1]));
}
__device__ __forceinline__ float fast_tanh(float x) {
    float e = __expf(2.0f * x);
    return 1.0f - 2.0f / (e + 1.0f);
}

// ---------------- pre-round inputs to tf32 (RNA) ----------------
__global__ void __launch_bounds__(256)
round_kernel(const float4* __restrict__ in, float4* __restrict__ out) {
    size_t i = (size_t)blockIdx.x * 2048 + threadIdx.x;
#pragma unroll
    for (int k = 0; k < 8; k++) {
        float4 v = in[i + (size_t)k * 256];
        v.x = rna_tf32(v.x); v.y = rna_tf32(v.y);
        v.z = rna_tf32(v.z); v.w = rna_tf32(v.w);
        out[i + (size_t)k * 256] = v;
    }
}

// ---------------- stage loader: A 128x32f, W 128x32f, rows padded to 144B ----------------
__device__ __forceinline__ void load_stage(const float* __restrict__ A,
                                           const float* __restrict__ W,
                                           int m0, int n0, int kc,
                                           uint32_t stA, uint32_t stB, int tid) {
#pragma unroll
    for (int it = 0; it < 8; it++) {             // 1024 x 16B for A
        int idx = tid + it * NTHREADS;
        int r = idx >> 3, c = idx & 7;
        cp16(stA + r * 144 + c * 16, A + (size_t)(m0 + r) * DDIM + kc * BK + c * 4);
    }
#pragma unroll
    for (int it = 0; it < 8; it++) {             // 1024 x 16B for W
        int idx = tid + it * NTHREADS;
        int r = idx >> 3, c = idx & 7;
        cp16(stB + r * 144 + c * 16, W + (size_t)(n0 + r) * DDIM + kc * BK + c * 4);
    }
}

// ---------------- shared mainloop: 4 warps, 64x64 warp tile ----------------
struct FragCtx {
    uint32_t s_base, a_off, b_off;
    int m0, n0, wm, wn;
};

__device__ __forceinline__ FragCtx make_ctx(uint32_t s_base, int tid) {
    const int lane = tid & 31;
    const int wid = tid >> 5;
    FragCtx fc;
    fc.s_base = s_base;
    fc.m0 = blockIdx.y * TILE_M;
    fc.n0 = blockIdx.x * TILE_N;
    fc.wm = (wid >> 1) * 64;                     // 2 warps along M
    fc.wn = (wid & 1) * 64;                      // 2 warps along N
    fc.a_off = (uint32_t)(fc.wm + ((lane >> 3) & 1) * 8 + (lane & 7)) * 144
               + (uint32_t)(lane >> 4) * 16;
    fc.b_off = (uint32_t)(fc.wn + (lane >> 4) * 8 + (lane & 7)) * 144
               + (uint32_t)((lane >> 3) & 1) * 16;
    return fc;
}

__device__ __forceinline__ void gemm_mainloop(const float* __restrict__ A,
                                              const float* __restrict__ W,
                                              const FragCtx& fc, int tid,
                                              float acc[4][8][4]) {
#pragma unroll
    for (int s = 0; s < STAGES - 1; s++) {
        load_stage(A, W, fc.m0, fc.n0, s,
                   fc.s_base + s * STAGE_FLOATS * 4,
                   fc.s_base + s * STAGE_FLOATS * 4 + A_FLOATS * 4, tid);
        asm volatile("cp.async.commit_group;" ::: "memory");
    }

    for (int i = 0; i < NCHUNK; i++) {
        asm volatile("cp.async.wait_group %0;" :: "n"(STAGES - 2));
        __syncthreads();

        const int j = i + STAGES - 1;
        if (j < NCHUNK) {
            load_stage(A, W, fc.m0, fc.n0, j,
                       fc.s_base + (j % STAGES) * STAGE_FLOATS * 4,
                       fc.s_base + (j % STAGES) * STAGE_FLOATS * 4 + A_FLOATS * 4, tid);
        }
        asm volatile("cp.async.commit_group;" ::: "memory");

        const uint32_t stA = fc.s_base + (i % STAGES) * STAGE_FLOATS * 4;
        const uint32_t stB = stA + A_FLOATS * 4;

#pragma unroll
        for (int kk = 0; kk < BK / 8; kk++) {    // 4 k8-steps per chunk
            uint32_t br[4][4];
#pragma unroll
            for (int g = 0; g < 4; g++)          // n-cols g*16..g*16+15
                ldsm4(br[g], stB + fc.b_off + g * 16 * 144 + kk * 32);
            uint32_t ar[4][4];
#pragma unroll
            for (int f = 0; f < 4; f++)          // m-rows f*16..f*16+15
                ldsm4(ar[f], stA + fc.a_off + f * 16 * 144 + kk * 32);
#pragma unroll
            for (int fm = 0; fm < 4; fm++) {
#pragma unroll
                for (int fn = 0; fn < 8; fn++) {
                    const uint32_t b2[2] = { br[fn >> 1][(fn & 1) * 2],
                                             br[fn >> 1][(fn & 1) * 2 + 1] };
                    mma8(acc[fm][fn], ar[fm], b2);
                }
            }
        }
    }
    asm volatile("cp.async.wait_group 0;" ::: "memory");
}

// ---------------- GEMM1: u = rna_tf32(tanh(h@W1^T + b1)) ----------------
__global__ void __launch_bounds__(NTHREADS, 2)
gemm1_kernel(const float* __restrict__ A, const float* __restrict__ W,
             const float* __restrict__ bias, float* __restrict__ C) {
    extern __shared__ float sm[];
    const int tid = threadIdx.x;
    const int lane = tid & 31;

    float acc[4][8][4];
#pragma unroll
    for (int i = 0; i < 4; i++)
#pragma unroll
        for (int j = 0; j < 8; j++)
#pragma unroll
            for (int k = 0; k < 4; k++) acc[i][j][k] = 0.0f;

    FragCtx fc = make_ctx(smem_u32(sm), tid);
    gemm_mainloop(A, W, fc, tid, acc);

    const int g = lane >> 2;
    const int tg = lane & 3;
#pragma unroll
    for (int fm = 0; fm < 4; fm++) {
        const int row = fc.m0 + fc.wm + fm * 16 + g;
#pragma unroll
        for (int fn = 0; fn < 8; fn++) {
            const int col = fc.n0 + fc.wn + fn * 8 + tg * 2;
            const float2 bb = *(const float2*)(bias + col);
            float v0 = rna_tf32(fast_tanh(acc[fm][fn][0] + bb.x));
            float v1 = rna_tf32(fast_tanh(acc[fm][fn][1] + bb.y));
            float v2 = rna_tf32(fast_tanh(acc[fm][fn][2] + bb.x));
            float v3 = rna_tf32(fast_tanh(acc[fm][fn][3] + bb.y));
            *(float2*)(C + (size_t)row * DDIM + col) = make_float2(v0, v1);
            *(float2*)(C + (size_t)(row + 8) * DDIM + col) = make_float2(v2, v3);
        }
    }
}

// ---------------- GEMM2 fused: s = u@W2^T, then per-tile softmax partials ----------------
__global__ void __launch_bounds__(NTHREADS, 2)
gemm2_fused_kernel(const float* __restrict__ A, const float* __restrict__ W,
                   const float* __restrict__ h) {
    extern __shared__ float sm[];
    const int tid = threadIdx.x;
    const int lane = tid & 31;

    float acc[4][8][4];
#pragma unroll
    for (int i = 0; i < 4; i++)
#pragma unroll
        for (int j = 0; j < 8; j++)
#pragma unroll
            for (int k = 0; k < 4; k++) acc[i][j][k] = 0.0f;

    FragCtx fc = make_ctx(smem_u32(sm), tid);
    gemm_mainloop(A, W, fc, tid, acc);
    __syncthreads();                              // pipeline smem now reusable

    // ---- dump s tile to smem: [row][col], stride 132 floats ----
    const int g = lane >> 2;
    const int tg = lane & 3;
#pragma unroll
    for (int fm = 0; fm < 4; fm++) {
        const int row = fc.wm + fm * 16 + g;
#pragma unroll
        for (int fn = 0; fn < 8; fn++) {
            const int col = fc.wn + fn * 8 + tg * 2;
            *(float2*)(sm + row * 132 + col) =
                make_float2(acc[fm][fn][0], acc[fm][fn][1]);
            *(float2*)(sm + (row + 8) * 132 + col) =
                make_float2(acc[fm][fn][2], acc[fm][fn][3]);
        }
    }
    __syncthreads();

    // ---- two-pass softmax partials per column (128 threads, 1 col each) ----
    const int col = tid;
    float M = -1e30f;
#pragma unroll 8
    for (int r = 0; r < 128; r++)
        M = fmaxf(M, sm[r * 132 + col]);

    const float* hp = h + (size_t)fc.m0 * DDIM + fc.n0 + col;
    float Z = 0.0f, Acc = 0.0f;
#pragma unroll 4
    for (int r = 0; r < 128; r++) {
        float p = __expf(sm[r * 132 + col] - M);
        Z += p;
        Acc += hp[(size_t)r * DDIM] * p;
    }

    const int b = blockIdx.y >> 5;
    const int ch = blockIdx.y & 31;
    const int idx = (b * CHUNKS + ch) * DDIM + fc.n0 + col;
    g_m[idx] = M;
    g_z[idx] = Z;
    g_a[idx] = Acc;
}

// ---------------- merges ----------------
__global__ void __launch_bounds__(128)
merge1_kernel() {
    const int d = blockIdx.x * 128 + threadIdx.x;
    const int b = blockIdx.y;
    float M = -1e30f;
#pragma unroll
    for (int c = 0; c < CHUNKS; c++)
        M = fmaxf(M, g_m[(b * CHUNKS + c) * DDIM + d]);
    float Z = 0.0f, Acc = 0.0f;
#pragma unroll
    for (int c = 0; c < CHUNKS; c++) {
        int idx = (b * CHUNKS + c) * DDIM + d;
        float e = __expf(g_m[idx] - M);
        Z += g_z[idx] * e;
        Acc += g_a[idx] * e;
    }
    g_r[b * DDIM + d] = Acc / Z;
}

__global__ void __launch_bounds__(128)
merge2_kernel(float* __restrict__ out) {
    const int d = blockIdx.x * 128 + threadIdx.x;
    float total = 0.0f;
#pragma unroll
    for (int b = 0; b < BDIM; b++) total += g_r[b * DDIM + d];
    out[d] = total;
}

// ---------------- host launcher ----------------
extern "C" void kernel_launch(void* const* d_in, const int* in_sizes, int n_in,
                              void* d_out, int out_size) {
    const float* h  = (const float*)d_in[0];
    const float* W1 = (const float*)d_in[1];
    const float* b1 = (const float*)d_in[2];
    const float* W2 = (const float*)d_in[3];
    float* out = (float*)d_out;

    float *hr, *w1r, *w2r, *u_ptr;
    cudaGetSymbolAddress((void**)&hr,    g_hr);
    cudaGetSymbolAddress((void**)&w1r,   g_w1);
    cudaGetSymbolAddress((void**)&w2r,   g_w2);
    cudaGetSymbolAddress((void**)&u_ptr, g_u);

    cudaFuncSetAttribute(gemm1_kernel,       cudaFuncAttributeMaxDynamicSharedMemorySize, SMEM_BYTES);
    cudaFuncSetAttribute(gemm2_fused_kernel, cudaFuncAttributeMaxDynamicSharedMemorySize, SMEM_BYTES);

    // pre-round to tf32 (RNA)
    round_kernel<<<(MDIM * (size_t)DDIM) / 8192, 256>>>((const float4*)h,  (float4*)hr);
    round_kernel<<<(DDIM * DDIM) / 8192, 256>>>((const float4*)W1, (float4*)w1r);
    round_kernel<<<(DDIM * DDIM) / 8192, 256>>>((const float4*)W2, (float4*)w2r);

    dim3 ggrid(DDIM / TILE_N, MDIM / TILE_M);    // (4, 1024)

    gemm1_kernel<<<ggrid, NTHREADS, SMEM_BYTES>>>(hr, w1r, b1, u_ptr);
    gemm2_fused_kernel<<<ggrid, NTHREADS, SMEM_BYTES>>>(u_ptr, w2r, h);

    dim3 m1grid(DDIM / 128, BDIM);
    merge1_kernel<<<m1grid, 128>>>();
    merge2_kernel<<<DDIM / 128, 128>>>(out);
}

// round 7
// speedup vs baseline: 1.3057x; 1.3057x over previous
#include <cuda_runtime.h>
#include <cstdint>

// ---------------- problem dims ----------------
#define BDIM 32
#define TDIM 4096
#define DDIM 512
#define MDIM (BDIM * TDIM)          // 131072

// ---------------- GEMM tiling ----------------
#define TILE_M 128
#define TILE_N 128
#define BK 32                        // k floats per chunk
#define NCHUNK (DDIM / BK)           // 16
#define STAGES 3
#define ROWF 36                      // padded row stride (144B = 9*16B -> conflict-free ldmatrix)
#define A_FLOATS (TILE_M * ROWF)     // 4608
#define B_FLOATS (TILE_N * ROWF)     // 4608
#define STAGE_FLOATS (A_FLOATS + B_FLOATS)       // 9216
#define SMEM_BYTES (STAGES * STAGE_FLOATS * 4)   // 110592

#define CHUNKS 32                    // softmax chunks = M-tiles per batch (4096/128)

// ---------------- scratch ----------------
__device__ float g_w1[DDIM * DDIM];           // tf32-rounded W1
__device__ float g_w2[DDIM * DDIM];           // tf32-rounded W2
__device__ float g_u[(size_t)MDIM * DDIM];    // tanh(...), tf32-rounded
__device__ float g_m[BDIM * CHUNKS * DDIM];
__device__ float g_z[BDIM * CHUNKS * DDIM];
__device__ float g_a[BDIM * CHUNKS * DDIM];
__device__ float g_r[BDIM * DDIM];

// ---------------- helpers ----------------
__device__ __forceinline__ uint32_t smem_u32(const void* p) {
    uint32_t a;
    asm("{ .reg .u64 t; cvta.to.shared.u64 t, %1; cvt.u32.u64 %0, t; }" : "=r"(a) : "l"(p));
    return a;
}
__device__ __forceinline__ void cp16(uint32_t dst, const void* src) {
    asm volatile("cp.async.cg.shared.global [%0], [%1], 16;" :: "r"(dst), "l"(src));
}
__device__ __forceinline__ void ldsm4(uint32_t* r, uint32_t addr) {
    asm volatile("ldmatrix.sync.aligned.m8n8.x4.shared.b16 {%0,%1,%2,%3}, [%4];"
                 : "=r"(r[0]), "=r"(r[1]), "=r"(r[2]), "=r"(r[3]) : "r"(addr));
}
__device__ __forceinline__ float rna_tf32(float x) {
    float y;
    asm("cvt.rna.tf32.f32 %0, %1;" : "=f"(y) : "f"(x));
    return y;
}
__device__ __forceinline__ uint32_t rna_tf32_u(uint32_t x) {
    uint32_t y;
    asm("cvt.rna.tf32.f32 %0, %1;" : "=r"(y) : "r"(x));
    return y;
}
__device__ __forceinline__ void mma8(float* c, const uint32_t* a, const uint32_t* b) {
    asm volatile(
        "mma.sync.aligned.m16n8k8.row.col.f32.tf32.tf32.f32 "
        "{%0,%1,%2,%3}, {%4,%5,%6,%7}, {%8,%9}, {%0,%1,%2,%3};"
        : "+f"(c[0]), "+f"(c[1]), "+f"(c[2]), "+f"(c[3])
        : "r"(a[0]), "r"(a[1]), "r"(a[2]), "r"(a[3]), "r"(b[0]), "r"(b[1]));
}
__device__ __forceinline__ float fast_tanh(float x) {
    float e = __expf(2.0f * x);
    return 1.0f - 2.0f / (e + 1.0f);
}

// ---------------- round W1 and W2 to tf32 (RNA), one launch ----------------
__global__ void __launch_bounds__(256)
round_w_kernel(const float4* __restrict__ w1, float4* __restrict__ w1o,
               const float4* __restrict__ w2, float4* __restrict__ w2o) {
    const float4* in  = (blockIdx.x < 32) ? w1  : w2;
    float4*       outp = (blockIdx.x < 32) ? w1o : w2o;
    size_t i = (size_t)(blockIdx.x & 31) * 2048 + threadIdx.x;
#pragma unroll
    for (int k = 0; k < 8; k++) {
        float4 v = in[i + (size_t)k * 256];
        v.x = rna_tf32(v.x); v.y = rna_tf32(v.y);
        v.z = rna_tf32(v.z); v.w = rna_tf32(v.w);
        outp[i + (size_t)k * 256] = v;
    }
}

// ---------------- stage loader: A 128x32f, W 128x32f, rows padded to 144B ----------------
__device__ __forceinline__ void load_stage(const float* __restrict__ A,
                                           const float* __restrict__ W,
                                           int m0, int n0, int kc,
                                           uint32_t stA, uint32_t stB, int tid) {
#pragma unroll
    for (int it = 0; it < 4; it++) {             // 1024 x 16B for A
        int idx = tid + it * 256;
        int r = idx >> 3, c = idx & 7;
        cp16(stA + r * 144 + c * 16, A + (size_t)(m0 + r) * DDIM + kc * BK + c * 4);
    }
#pragma unroll
    for (int it = 0; it < 4; it++) {             // 1024 x 16B for W
        int idx = tid + it * 256;
        int r = idx >> 3, c = idx & 7;
        cp16(stB + r * 144 + c * 16, W + (size_t)(n0 + r) * DDIM + kc * BK + c * 4);
    }
}

// ---------------- shared mainloop: 8 warps, 64x32 warp tile ----------------
struct FragCtx {
    uint32_t s_base, a_off, b_off;
    int m0, n0, wm, wn;
};

__device__ __forceinline__ FragCtx make_ctx(uint32_t s_base, int tid) {
    const int lane = tid & 31;
    const int wid = tid >> 5;
    FragCtx fc;
    fc.s_base = s_base;
    fc.m0 = blockIdx.y * TILE_M;
    fc.n0 = blockIdx.x * TILE_N;
    fc.wm = (wid >> 2) * 64;                     // 2 warps along M
    fc.wn = (wid & 3) * 32;                      // 4 warps along N
    fc.a_off = (uint32_t)(fc.wm + ((lane >> 3) & 1) * 8 + (lane & 7)) * 144
               + (uint32_t)(lane >> 4) * 16;
    fc.b_off = (uint32_t)(fc.wn + (lane >> 4) * 8 + (lane & 7)) * 144
               + (uint32_t)((lane >> 3) & 1) * 16;
    return fc;
}

// CVT_A: apply cvt.rna.tf32 to A fragments after ldmatrix (raw-fp32 A input).
template <bool CVT_A>
__device__ __forceinline__ void gemm_mainloop(const float* __restrict__ A,
                                              const float* __restrict__ W,
                                              const FragCtx& fc, int tid,
                                              float acc[4][4][4]) {
#pragma unroll
    for (int s = 0; s < STAGES - 1; s++) {
        load_stage(A, W, fc.m0, fc.n0, s,
                   fc.s_base + s * STAGE_FLOATS * 4,
                   fc.s_base + s * STAGE_FLOATS * 4 + A_FLOATS * 4, tid);
        asm volatile("cp.async.commit_group;" ::: "memory");
    }

    for (int i = 0; i < NCHUNK; i++) {
        asm volatile("cp.async.wait_group %0;" :: "n"(STAGES - 2));
        __syncthreads();

        const int j = i + STAGES - 1;
        if (j < NCHUNK) {
            load_stage(A, W, fc.m0, fc.n0, j,
                       fc.s_base + (j % STAGES) * STAGE_FLOATS * 4,
                       fc.s_base + (j % STAGES) * STAGE_FLOATS * 4 + A_FLOATS * 4, tid);
        }
        asm volatile("cp.async.commit_group;" ::: "memory");

        const uint32_t stA = fc.s_base + (i % STAGES) * STAGE_FLOATS * 4;
        const uint32_t stB = stA + A_FLOATS * 4;

#pragma unroll
        for (int kk = 0; kk < BK / 8; kk++) {    // 4 k8-steps per chunk
            uint32_t br[2][4];
#pragma unroll
            for (int g = 0; g < 2; g++)
                ldsm4(br[g], stB + fc.b_off + g * 16 * 144 + kk * 32);
            uint32_t ar[4][4];
#pragma unroll
            for (int f = 0; f < 4; f++) {
                ldsm4(ar[f], stA + fc.a_off + f * 16 * 144 + kk * 32);
                if (CVT_A) {
#pragma unroll
                    for (int t = 0; t < 4; t++) ar[f][t] = rna_tf32_u(ar[f][t]);
                }
            }
#pragma unroll
            for (int fm = 0; fm < 4; fm++) {
#pragma unroll
                for (int fn = 0; fn < 4; fn++) {
                    const uint32_t b2[2] = { br[fn >> 1][(fn & 1) * 2],
                                             br[fn >> 1][(fn & 1) * 2 + 1] };
                    mma8(acc[fm][fn], ar[fm], b2);
                }
            }
        }
    }
    asm volatile("cp.async.wait_group 0;" ::: "memory");
}

// ---------------- GEMM1: u = rna_tf32(tanh(h@W1^T + b1)), raw-h input ----------------
__global__ void __launch_bounds__(256, 2)
gemm1_kernel(const float* __restrict__ A, const float* __restrict__ W,
             const float* __restrict__ bias, float* __restrict__ C) {
    extern __shared__ float sm[];
    const int tid = threadIdx.x;
    const int lane = tid & 31;

    float acc[4][4][4];
#pragma unroll
    for (int i = 0; i < 4; i++)
#pragma unroll
        for (int j = 0; j < 4; j++)
#pragma unroll
            for (int k = 0; k < 4; k++) acc[i][j][k] = 0.0f;

    FragCtx fc = make_ctx(smem_u32(sm), tid);
    gemm_mainloop<true>(A, W, fc, tid, acc);

    const int g = lane >> 2;
    const int tg = lane & 3;
#pragma unroll
    for (int fm = 0; fm < 4; fm++) {
        const int row = fc.m0 + fc.wm + fm * 16 + g;
#pragma unroll
        for (int fn = 0; fn < 4; fn++) {
            const int col = fc.n0 + fc.wn + fn * 8 + tg * 2;
            const float2 bb = *(const float2*)(bias + col);
            float v0 = rna_tf32(fast_tanh(acc[fm][fn][0] + bb.x));
            float v1 = rna_tf32(fast_tanh(acc[fm][fn][1] + bb.y));
            float v2 = rna_tf32(fast_tanh(acc[fm][fn][2] + bb.x));
            float v3 = rna_tf32(fast_tanh(acc[fm][fn][3] + bb.y));
            *(float2*)(C + (size_t)row * DDIM + col) = make_float2(v0, v1);
            *(float2*)(C + (size_t)(row + 8) * DDIM + col) = make_float2(v2, v3);
        }
    }
}

// ---------------- GEMM2 fused: s = u@W2^T, then per-tile softmax partials ----------------
__global__ void __launch_bounds__(256, 2)
gemm2_fused_kernel(const float* __restrict__ A, const float* __restrict__ W,
                   const float* __restrict__ h) {
    extern __shared__ float sm[];
    const int tid = threadIdx.x;
    const int lane = tid & 31;

    float acc[4][4][4];
#pragma unroll
    for (int i = 0; i < 4; i++)
#pragma unroll
        for (int j = 0; j < 4; j++)
#pragma unroll
            for (int k = 0; k < 4; k++) acc[i][j][k] = 0.0f;

    FragCtx fc = make_ctx(smem_u32(sm), tid);
    gemm_mainloop<false>(A, W, fc, tid, acc);
    __syncthreads();                              // pipeline smem now reusable

    // ---- dump s tile to smem: [row][col], stride 132 floats ----
    const int g = lane >> 2;
    const int tg = lane & 3;
#pragma unroll
    for (int fm = 0; fm < 4; fm++) {
        const int row = fc.wm + fm * 16 + g;
#pragma unroll
        for (int fn = 0; fn < 4; fn++) {
            const int col = fc.wn + fn * 8 + tg * 2;
            *(float2*)(sm + row * 132 + col) =
                make_float2(acc[fm][fn][0], acc[fm][fn][1]);
            *(float2*)(sm + (row + 8) * 132 + col) =
                make_float2(acc[fm][fn][2], acc[fm][fn][3]);
        }
    }
    __syncthreads();

    // ---- per-column two-pass softmax over 64 rows + weighted h (2 halves) ----
    const int col = tid & 127;
    const int half = tid >> 7;
    const float* hp = h + (size_t)(fc.m0 + half * 64) * DDIM + fc.n0 + col;

    float m = -1e30f;
#pragma unroll 8
    for (int r = 0; r < 64; r++)
        m = fmaxf(m, sm[(half * 64 + r) * 132 + col]);

    float Z = 0.0f, accv = 0.0f;
#pragma unroll 4
    for (int r = 0; r < 64; r++) {
        float p = __expf(sm[(half * 64 + r) * 132 + col] - m);
        Z += p;
        accv += hp[(size_t)r * DDIM] * p;
    }

    // ---- merge the two halves ----
    float* red = sm + 128 * 132;                  // 768 floats scratch
    red[half * 128 + col] = m;
    red[256 + half * 128 + col] = Z;
    red[512 + half * 128 + col] = accv;
    __syncthreads();

    if (tid < 128) {
        float ma = red[tid], mb = red[128 + tid];
        float M = fmaxf(ma, mb);
        float ea = __expf(ma - M), eb = __expf(mb - M);
        float Zt = red[256 + tid] * ea + red[384 + tid] * eb;
        float At = red[512 + tid] * ea + red[640 + tid] * eb;
        const int b = blockIdx.y >> 5;
        const int ch = blockIdx.y & 31;
        const int idx = (b * CHUNKS + ch) * DDIM + fc.n0 + tid;
        g_m[idx] = M;
        g_z[idx] = Zt;
        g_a[idx] = At;
    }
}

// ---------------- merges ----------------
__global__ void __launch_bounds__(128)
merge1_kernel() {
    const int d = blockIdx.x * 128 + threadIdx.x;
    const int b = blockIdx.y;
    float M = -1e30f;
#pragma unroll
    for (int c = 0; c < CHUNKS; c++)
        M = fmaxf(M, g_m[(b * CHUNKS + c) * DDIM + d]);
    float Z = 0.0f, Acc = 0.0f;
#pragma unroll
    for (int c = 0; c < CHUNKS; c++) {
        int idx = (b * CHUNKS + c) * DDIM + d;
        float e = __expf(g_m[idx] - M);
        Z += g_z[idx] * e;
        Acc += g_a[idx] * e;
    }
    g_r[b * DDIM + d] = Acc / Z;
}

__global__ void __launch_bounds__(128)
merge2_kernel(float* __restrict__ out) {
    const int d = blockIdx.x * 128 + threadIdx.x;
    float total = 0.0f;
#pragma unroll
    for (int b = 0; b < BDIM; b++) total += g_r[b * DDIM + d];
    out[d] = total;
}

// ---------------- host launcher ----------------
extern "C" void kernel_launch(void* const* d_in, const int* in_sizes, int n_in,
                              void* d_out, int out_size) {
    const float* h  = (const float*)d_in[0];
    const float* W1 = (const float*)d_in[1];
    const float* b1 = (const float*)d_in[2];
    const float* W2 = (const float*)d_in[3];
    float* out = (float*)d_out;

    float *w1r, *w2r, *u_ptr;
    cudaGetSymbolAddress((void**)&w1r,   g_w1);
    cudaGetSymbolAddress((void**)&w2r,   g_w2);
    cudaGetSymbolAddress((void**)&u_ptr, g_u);

    cudaFuncSetAttribute(gemm1_kernel,       cudaFuncAttributeMaxDynamicSharedMemorySize, SMEM_BYTES);
    cudaFuncSetAttribute(gemm2_fused_kernel, cudaFuncAttributeMaxDynamicSharedMemorySize, SMEM_BYTES);

    // round W1+W2 to tf32 (RNA); h is rounded in-loop inside gemm1
    round_w_kernel<<<64, 256>>>((const float4*)W1, (float4*)w1r,
                                (const float4*)W2, (float4*)w2r);

    dim3 ggrid(DDIM / TILE_N, MDIM / TILE_M);    // (4, 1024)

    gemm1_kernel<<<ggrid, 256, SMEM_BYTES>>>(h, w1r, b1, u_ptr);
    gemm2_fused_kernel<<<ggrid, 256, SMEM_BYTES>>>(u_ptr, w2r, h);

    dim3 m1grid(DDIM / 128, BDIM);
    merge1_kernel<<<m1grid, 128>>>();
    merge2_kernel<<<DDIM / 128, 128>>>(out);
}